// round 2
// baseline (speedup 1.0000x reference)
#include <cuda_runtime.h>

#define BATCH 4
#define CH    256
#define CQ    32
#define NPIX  4096

// -------- scratch (device globals; no allocations allowed) --------
__device__ __align__(16) float g_q[BATCH * CQ * NPIX];   // [b][d][n] centered
__device__ __align__(16) float g_k[BATCH * CQ * NPIX];   // [b][d][n] centered
__device__ __align__(16) float g_v[BATCH * CH * NPIX];   // [b][c][n] relu'd
__device__ __align__(16) float g_mask[BATCH * NPIX];     // pm -> softmax mask
__device__ __align__(16) float g_mv[BATCH * CH];         // V @ mask

// ============================================================
// Projections: one combined GEMM  W[321x256] @ X[256x4096] per batch.
// rows 0..31 -> q, 32..63 -> k, 64..319 -> v (+bias,relu), 320 -> pm (+bias)
// q/k biases are skipped: they cancel under spatial centering.
// grid (N/64, 6 row-groups, B), block 256, 4x4 register tiles.
// ============================================================
__global__ __launch_bounds__(256) void proj_kernel(
    const float* __restrict__ x,
    const float* __restrict__ wq, const float* __restrict__ wk,
    const float* __restrict__ wv, const float* __restrict__ bv,
    const float* __restrict__ wm, const float* __restrict__ bm)
{
    __shared__ float Xs[64][68];
    __shared__ float Wst[64][68];   // transposed: Wst[ci][r]
    const int b  = blockIdx.z;
    const int n0 = blockIdx.x * 64;
    const int r0 = blockIdx.y * 64;
    const int t  = threadIdx.x;
    const int tr = t >> 4, tc = t & 15;
    const float* xb = x + (size_t)b * CH * NPIX;

    float acc[16];
#pragma unroll
    for (int i = 0; i < 16; i++) acc[i] = 0.f;

    for (int cc = 0; cc < 4; cc++) {
#pragma unroll
        for (int it = 0; it < 16; it++) {
            int e = t + 256 * it;
            int ci = e >> 6, nj = e & 63;
            Xs[ci][nj] = xb[(size_t)(cc * 64 + ci) * NPIX + n0 + nj];
        }
#pragma unroll
        for (int it = 0; it < 16; it++) {
            int e = t + 256 * it;
            int r = e >> 6, ci = e & 63;
            int gr = r0 + r;
            int c  = cc * 64 + ci;
            float wval = 0.f;
            if (gr < 32)        wval = wq[gr * CH + c];
            else if (gr < 64)   wval = wk[(gr - 32) * CH + c];
            else if (gr < 320)  wval = wv[(gr - 64) * CH + c];
            else if (gr == 320) wval = wm[c];
            Wst[ci][r] = wval;
        }
        __syncthreads();
#pragma unroll
        for (int ci = 0; ci < 64; ci++) {
            float4 a  = *(const float4*)&Wst[ci][tr * 4];
            float4 xv = *(const float4*)&Xs[ci][tc * 4];
            float a4[4] = {a.x, a.y, a.z, a.w};
            float x4[4] = {xv.x, xv.y, xv.z, xv.w};
#pragma unroll
            for (int i = 0; i < 4; i++)
#pragma unroll
                for (int j = 0; j < 4; j++) acc[i * 4 + j] += a4[i] * x4[j];
        }
        __syncthreads();
    }

#pragma unroll
    for (int i = 0; i < 4; i++) {
        int gr = r0 + tr * 4 + i;
        if (gr > 320) continue;
#pragma unroll
        for (int j = 0; j < 4; j++) {
            int n = n0 + tc * 4 + j;
            float val = acc[i * 4 + j];
            if (gr < 32)       g_q[((size_t)b * CQ + gr) * NPIX + n] = val;
            else if (gr < 64)  g_k[((size_t)b * CQ + gr - 32) * NPIX + n] = val;
            else if (gr < 320) {
                int c2 = gr - 64;
                g_v[((size_t)b * CH + c2) * NPIX + n] = fmaxf(val + bv[c2], 0.f);
            } else {
                g_mask[(size_t)b * NPIX + n] = val + bm[0];
            }
        }
    }
}

// ============================================================
// Center q and k rows over the spatial dim (mean over 4096).
// grid (64 rows, B): rows 0..31 -> q, 32..63 -> k
// ============================================================
__global__ __launch_bounds__(256) void center_kernel()
{
    const int b = blockIdx.y, r = blockIdx.x;
    float* p = (r < 32) ? (g_q + ((size_t)b * CQ + r) * NPIX)
                        : (g_k + ((size_t)b * CQ + r - 32) * NPIX);
    __shared__ float red[256];
    const int t = threadIdx.x;
    float s = 0.f;
    for (int i = t; i < NPIX; i += 256) s += p[i];
    red[t] = s; __syncthreads();
    for (int st = 128; st > 0; st >>= 1) {
        if (t < st) red[t] += red[t + st];
        __syncthreads();
    }
    float mean = red[0] * (1.f / NPIX);
    for (int i = t; i < NPIX; i += 256) p[i] -= mean;
}

// ============================================================
// Softmax over N for the mask logits (in place in g_mask). grid (B)
// ============================================================
__global__ __launch_bounds__(256) void mask_softmax_kernel()
{
    const int b = blockIdx.x;
    float* pm = g_mask + (size_t)b * NPIX;
    __shared__ float red[256];
    const int t = threadIdx.x;
    float mx = -1e30f;
    for (int i = t; i < NPIX; i += 256) mx = fmaxf(mx, pm[i]);
    red[t] = mx; __syncthreads();
    for (int st = 128; st > 0; st >>= 1) {
        if (t < st) red[t] = fmaxf(red[t], red[t + st]);
        __syncthreads();
    }
    mx = red[0];
    __syncthreads();
    float s = 0.f;
    for (int i = t; i < NPIX; i += 256) s += __expf(pm[i] - mx);
    red[t] = s; __syncthreads();
    for (int st = 128; st > 0; st >>= 1) {
        if (t < st) red[t] += red[t + st];
        __syncthreads();
    }
    float inv = 1.f / red[0];
    for (int i = t; i < NPIX; i += 256) pm[i] = __expf(pm[i] - mx) * inv;
}

// ============================================================
// mv[b][c] = sum_n v[b][c][n] * mask[b][n].  grid (CH, B), block 128.
// ============================================================
__global__ __launch_bounds__(128) void mv_kernel()
{
    const int b = blockIdx.y, c = blockIdx.x;
    const float* vp = g_v + ((size_t)b * CH + c) * NPIX;
    const float* mk = g_mask + (size_t)b * NPIX;
    __shared__ float red[128];
    const int t = threadIdx.x;
    float s = 0.f;
    for (int i = t; i < NPIX; i += 128) s += vp[i] * mk[i];
    red[t] = s; __syncthreads();
    for (int st = 64; st > 0; st >>= 1) {
        if (t < st) red[t] += red[t + st];
        __syncthreads();
    }
    if (t == 0) g_mv[b * CH + c] = red[0];
}

// ============================================================
// Attention: per (b, 64-row m-tile), stream n in chunks of 64:
//   S = q_tile^T k_chunk (32-d inner), E = exp(S) in smem, rowsum accum,
//   O += E @ Vchunk^T with V chunk staged in smem.
// Epilogue: O[m][c]/rowsum[m] + mv[c], transposed through smem for
// coalesced [b][c][m] stores. Energies are small -> plain exp is safe.
// ============================================================
__global__ __launch_bounds__(256) void attn_kernel(float* __restrict__ out_t)
{
    extern __shared__ float sm[];
    float* qs     = sm;                    // [32][64]
    float* ks     = sm + 2048;             // [32][64]
    float* Es     = sm + 4096;             // [64][64]
    float* vsm    = sm + 8192;             // [256][65]  (reused for epilogue transpose)
    float* rowsum = sm + 8192 + 16640;     // [64]

    const int b  = blockIdx.y;
    const int m0 = blockIdx.x * 64;
    const int t  = threadIdx.x;
    const int w  = t >> 5, l = t & 31;     // EV phase: warp owns 8 m-rows, lane owns 8 c
    const int tm4 = t >> 4, tn4 = t & 15;  // S phase: 4m x 4n per thread
    const float* qb = g_q + (size_t)b * CQ * NPIX;
    const float* kb = g_k + (size_t)b * CQ * NPIX;
    const float* vb = g_v + (size_t)b * CH * NPIX;

#pragma unroll
    for (int it = 0; it < 8; it++) {
        int e = t + 256 * it; int d = e >> 6, m = e & 63;
        qs[d * 64 + m] = qb[(size_t)d * NPIX + m0 + m];
    }
    if (t < 64) rowsum[t] = 0.f;

    float acc[64];
#pragma unroll
    for (int i = 0; i < 64; i++) acc[i] = 0.f;
    __syncthreads();

    for (int n0 = 0; n0 < NPIX; n0 += 64) {
        // ---- stage k chunk and v chunk ----
#pragma unroll
        for (int it = 0; it < 8; it++) {
            int e = t + 256 * it; int d = e >> 6, nj = e & 63;
            ks[d * 64 + nj] = kb[(size_t)d * NPIX + n0 + nj];
        }
#pragma unroll
        for (int it = 0; it < 16; it++) {
            int e = t + 256 * it; int c = e >> 4, nq = e & 15;
            float4 vv = *(const float4*)&vb[(size_t)c * NPIX + n0 + nq * 4];
            float* dst = &vsm[c * 65 + nq * 4];
            dst[0] = vv.x; dst[1] = vv.y; dst[2] = vv.z; dst[3] = vv.w;
        }
        __syncthreads();

        // ---- S = q^T k, exp, rowsum ----
        {
            float s[16];
#pragma unroll
            for (int i = 0; i < 16; i++) s[i] = 0.f;
#pragma unroll
            for (int d = 0; d < 32; d++) {
                float4 qv = *(const float4*)&qs[d * 64 + tm4 * 4];
                float4 kv = *(const float4*)&ks[d * 64 + tn4 * 4];
                float qa[4] = {qv.x, qv.y, qv.z, qv.w};
                float ka[4] = {kv.x, kv.y, kv.z, kv.w};
#pragma unroll
                for (int i = 0; i < 4; i++)
#pragma unroll
                    for (int j = 0; j < 4; j++) s[i * 4 + j] += qa[i] * ka[j];
            }
#pragma unroll
            for (int i = 0; i < 4; i++) {
                float rs = 0.f;
#pragma unroll
                for (int j = 0; j < 4; j++) {
                    float ev = __expf(s[i * 4 + j]);
                    Es[(tm4 * 4 + i) * 64 + tn4 * 4 + j] = ev;
                    rs += ev;
                }
                atomicAdd(&rowsum[tm4 * 4 + i], rs);
            }
        }
        __syncthreads();

        // ---- O += E @ Vchunk^T ----
#pragma unroll 2
        for (int nj = 0; nj < 64; nj++) {
            float ev[8], vvv[8];
#pragma unroll
            for (int i = 0; i < 8; i++) ev[i] = Es[(w * 8 + i) * 64 + nj];
#pragma unroll
            for (int j = 0; j < 8; j++) vvv[j] = vsm[(l + 32 * j) * 65 + nj];
#pragma unroll
            for (int i = 0; i < 8; i++)
#pragma unroll
                for (int j = 0; j < 8; j++) acc[i * 8 + j] += ev[i] * vvv[j];
        }
        __syncthreads();
    }

    // ---- epilogue: normalize, transpose through smem, coalesced store ----
#pragma unroll
    for (int i = 0; i < 8; i++) {
        float inv = 1.f / rowsum[w * 8 + i];
#pragma unroll
        for (int j = 0; j < 8; j++)
            vsm[(l + 32 * j) * 65 + (w * 8 + i)] = acc[i * 8 + j] * inv;
    }
    __syncthreads();

    const float* mvb = g_mv + b * CH;
    float* ob = out_t + (size_t)b * CH * NPIX + m0;
    int mj = t & 63, cg = t >> 6;
    for (int c = cg; c < CH; c += 4)
        ob[(size_t)c * NPIX + mj] = vsm[c * 65 + mj] + mvb[c];
}

// ============================================================
extern "C" void kernel_launch(void* const* d_in, const int* in_sizes, int n_in,
                              void* d_out, int out_size)
{
    const float* x  = (const float*)d_in[0];
    const float* wq = (const float*)d_in[1];
    const float* wk = (const float*)d_in[3];
    const float* wv = (const float*)d_in[5];
    const float* bv = (const float*)d_in[6];
    const float* wm = (const float*)d_in[7];
    const float* bm = (const float*)d_in[8];
    float* out = (float*)d_out;

    const size_t half = (size_t)BATCH * CH * NPIX;  // 4,194,304
    float* tissue = out + ((size_t)out_size - half);
    if ((size_t)out_size >= 2 * half)
        cudaMemcpyAsync(out, x, half * sizeof(float), cudaMemcpyDeviceToDevice);

    proj_kernel<<<dim3(64, 6, 4), 256>>>(x, wq, wk, wv, bv, wm, bm);
    center_kernel<<<dim3(64, 4), 256>>>();
    mask_softmax_kernel<<<4, 256>>>();
    mv_kernel<<<dim3(256, 4), 128>>>();

    const int SMEM_ATTN = (2048 + 2048 + 4096 + 16640 + 64) * 4;  // 99584 B
    cudaFuncSetAttribute(attn_kernel, cudaFuncAttributeMaxDynamicSharedMemorySize,
                         SMEM_ATTN);
    attn_kernel<<<dim3(64, 4), 256, SMEM_ATTN>>>(tissue);
}

// round 17
// speedup vs baseline: 2.6260x; 2.6260x over previous
#include <cuda_runtime.h>
#include <cuda_bf16.h>
#include <mma.h>
#include <cstdint>

using namespace nvcuda;

#define BATCH 4
#define CH    256
#define CQ    32
#define NPIX  4096

// -------- scratch (device globals; zero-initialized, no allocations) --------
__device__ __align__(16) float g_q[BATCH * CQ * NPIX];            // [b][d][n] fp32 (pre-center)
__device__ __align__(16) float g_k[BATCH * CQ * NPIX];            // [b][d][n] fp32 (pre-center)
__device__ __align__(16) __nv_bfloat16 g_qT[BATCH * NPIX * 64];   // [b][m][64] bf16, d in cols 0..31
__device__ __align__(16) __nv_bfloat16 g_kT[BATCH * NPIX * 64];   // [b][n][64] bf16, d in cols 0..31
__device__ __align__(16) __nv_bfloat16 g_vb[BATCH * CH * NPIX];   // [b][c][n] bf16, relu'd
__device__ __align__(16) float g_mask[BATCH * NPIX];
__device__ __align__(16) float g_mv[BATCH * CH];

// ============================================================
// Projections: W[321x256] @ X[256x4096] per batch (fp32).
// ============================================================
__global__ __launch_bounds__(256) void proj_kernel(
    const float* __restrict__ x,
    const float* __restrict__ wq, const float* __restrict__ wk,
    const float* __restrict__ wv, const float* __restrict__ bv,
    const float* __restrict__ wm, const float* __restrict__ bm)
{
    __shared__ float Xs[64][68];
    __shared__ float Wst[64][68];
    const int b  = blockIdx.z;
    const int n0 = blockIdx.x * 64;
    const int r0 = blockIdx.y * 64;
    const int t  = threadIdx.x;
    const int tr = t >> 4, tc = t & 15;
    const float* xb = x + (size_t)b * CH * NPIX;

    float acc[16];
#pragma unroll
    for (int i = 0; i < 16; i++) acc[i] = 0.f;

    for (int cc = 0; cc < 4; cc++) {
#pragma unroll
        for (int it = 0; it < 16; it++) {
            int e = t + 256 * it;
            int ci = e >> 6, nj = e & 63;
            Xs[ci][nj] = xb[(size_t)(cc * 64 + ci) * NPIX + n0 + nj];
        }
#pragma unroll
        for (int it = 0; it < 16; it++) {
            int e = t + 256 * it;
            int r = e >> 6, ci = e & 63;
            int gr = r0 + r;
            int c  = cc * 64 + ci;
            float wval = 0.f;
            if (gr < 32)        wval = wq[gr * CH + c];
            else if (gr < 64)   wval = wk[(gr - 32) * CH + c];
            else if (gr < 320)  wval = wv[(gr - 64) * CH + c];
            else if (gr == 320) wval = wm[c];
            Wst[ci][r] = wval;
        }
        __syncthreads();
#pragma unroll
        for (int ci = 0; ci < 64; ci++) {
            float4 a  = *(const float4*)&Wst[ci][tr * 4];
            float4 xv = *(const float4*)&Xs[ci][tc * 4];
            float a4[4] = {a.x, a.y, a.z, a.w};
            float x4[4] = {xv.x, xv.y, xv.z, xv.w};
#pragma unroll
            for (int i = 0; i < 4; i++)
#pragma unroll
                for (int j = 0; j < 4; j++) acc[i * 4 + j] += a4[i] * x4[j];
        }
        __syncthreads();
    }

#pragma unroll
    for (int i = 0; i < 4; i++) {
        int gr = r0 + tr * 4 + i;
        if (gr > 320) continue;
#pragma unroll
        for (int j = 0; j < 4; j++) {
            int n = n0 + tc * 4 + j;
            float val = acc[i * 4 + j];
            if (gr < 32)       g_q[((size_t)b * CQ + gr) * NPIX + n] = val;
            else if (gr < 64)  g_k[((size_t)b * CQ + gr - 32) * NPIX + n] = val;
            else if (gr < 320) {
                int c2 = gr - 64;
                g_vb[((size_t)b * CH + c2) * NPIX + n] =
                    __float2bfloat16(fmaxf(val + bv[c2], 0.f));
            } else {
                g_mask[(size_t)b * NPIX + n] = val + bm[0];
            }
        }
    }
}

// ============================================================
// Center q/k rows over N, write transposed bf16 [n][64] tiles.
// grid (64 rows, B): rows 0..31 -> q, 32..63 -> k
// ============================================================
__global__ __launch_bounds__(256) void center_qk_kernel()
{
    const int b = blockIdx.y, r = blockIdx.x;
    const int d = r & 31;
    const float* src = (r < 32) ? (g_q + ((size_t)b * CQ + d) * NPIX)
                                : (g_k + ((size_t)b * CQ + d) * NPIX);
    __nv_bfloat16* dst = ((r < 32) ? g_qT : g_kT) + (size_t)b * NPIX * 64 + d;
    __shared__ float red[256];
    const int t = threadIdx.x;
    float s = 0.f;
    for (int i = t; i < NPIX; i += 256) s += src[i];
    red[t] = s; __syncthreads();
    for (int st = 128; st > 0; st >>= 1) {
        if (t < st) red[t] += red[t + st];
        __syncthreads();
    }
    float mean = red[0] * (1.f / NPIX);
    for (int i = t; i < NPIX; i += 256)
        dst[(size_t)i * 64] = __float2bfloat16(src[i] - mean);
}

// ============================================================
// Softmax over N for the mask logits (in place). grid (B)
// ============================================================
__global__ __launch_bounds__(256) void mask_softmax_kernel()
{
    const int b = blockIdx.x;
    float* pm = g_mask + (size_t)b * NPIX;
    __shared__ float red[256];
    const int t = threadIdx.x;
    float mx = -1e30f;
    for (int i = t; i < NPIX; i += 256) mx = fmaxf(mx, pm[i]);
    red[t] = mx; __syncthreads();
    for (int st = 128; st > 0; st >>= 1) {
        if (t < st) red[t] = fmaxf(red[t], red[t + st]);
        __syncthreads();
    }
    mx = red[0];
    __syncthreads();
    float s = 0.f;
    for (int i = t; i < NPIX; i += 256) s += __expf(pm[i] - mx);
    red[t] = s; __syncthreads();
    for (int st = 128; st > 0; st >>= 1) {
        if (t < st) red[t] += red[t + st];
        __syncthreads();
    }
    float inv = 1.f / red[0];
    for (int i = t; i < NPIX; i += 256) pm[i] = __expf(pm[i] - mx) * inv;
}

// ============================================================
// mv[b][c] = sum_n v[b][c][n] * mask[b][n].  grid (CH, B)
// ============================================================
__global__ __launch_bounds__(128) void mv_kernel()
{
    const int b = blockIdx.y, c = blockIdx.x;
    const __nv_bfloat16* vp = g_vb + ((size_t)b * CH + c) * NPIX;
    const float* mk = g_mask + (size_t)b * NPIX;
    __shared__ float red[128];
    const int t = threadIdx.x;
    float s = 0.f;
    for (int i = t; i < NPIX; i += 128) s += __bfloat162float(vp[i]) * mk[i];
    red[t] = s; __syncthreads();
    for (int st = 64; st > 0; st >>= 1) {
        if (t < st) red[t] += red[t + st];
        __syncthreads();
    }
    if (t == 0) g_mv[b * CH + c] = red[0];
}

// ============================================================
// WMMA (HMMA) attention. grid (NPIX/64, B), 256 threads = 8 warps.
// Per CTA: 64 m-rows. Loop 64 n-chunks of 64:
//   S[64x64] = Q Kt via wmma (A=g_qT row-major, B=g_kT col-major)
//   exp -> Es bf16 smem + per-row partial sums
//   O[64x256] += E @ V^T: A=Es, B loaded straight from g_vb col-major.
// O lives in 8 accumulator fragments per warp across all chunks.
// SMEM layout (dynamic, 67840 B):
//   loop:     Ss fp32 [64][68] @0 (17408B), Es bf16 [64][72] @17408 (9216B)
//   epilogue: Ep fp32 [64][260] @0 (66560B)  -- overlays Ss/Es
//   rsp  fp32 [64*4] @66560
// ============================================================
__global__ __launch_bounds__(256) void attn_wmma_kernel(float* __restrict__ out_t)
{
    extern __shared__ char sm[];
    float* Ss  = (float*)sm;                              // [64][68]
    __nv_bfloat16* Es = (__nv_bfloat16*)(sm + 17408);     // [64][72]
    float* Ep  = (float*)sm;                              // [64][260] (epilogue)
    float* rsp = (float*)(sm + 66560);                    // [64*4]

    const int t = threadIdx.x, w = t >> 5;
    const int b = blockIdx.y, m0 = blockIdx.x * 64;
    const int c0 = w * 32;                                // warp's c-group

    rsp[t] = 0.f;
    __syncthreads();

    const __nv_bfloat16* qb = g_qT + (size_t)(b * NPIX + m0) * 64;
    const __nv_bfloat16* kb = g_kT + (size_t)b * NPIX * 64;
    const __nv_bfloat16* vb = g_vb + (size_t)b * CH * NPIX;

    wmma::fragment<wmma::accumulator, 16, 16, 16, float> oacc[4][2];
#pragma unroll
    for (int mt = 0; mt < 4; mt++)
#pragma unroll
        for (int cg = 0; cg < 2; cg++)
            wmma::fill_fragment(oacc[mt][cg], 0.f);

    for (int ch = 0; ch < NPIX / 64; ch++) {
        const int n0 = ch * 64;

        // ---- S phase: 16 tiles (4x4), 2 per warp ----
#pragma unroll
        for (int i = 0; i < 2; i++) {
            int tIdx = w * 2 + i;
            int tr = tIdx >> 2, tc = tIdx & 3;
            wmma::fragment<wmma::accumulator, 16, 16, 16, float> sacc;
            wmma::fill_fragment(sacc, 0.f);
#pragma unroll
            for (int kk = 0; kk < 2; kk++) {
                wmma::fragment<wmma::matrix_a, 16, 16, 16, __nv_bfloat16, wmma::row_major> fa;
                wmma::fragment<wmma::matrix_b, 16, 16, 16, __nv_bfloat16, wmma::col_major> fb;
                wmma::load_matrix_sync(fa, qb + (size_t)(tr * 16) * 64 + kk * 16, 64);
                wmma::load_matrix_sync(fb, kb + (size_t)(n0 + tc * 16) * 64 + kk * 16, 64);
                wmma::mma_sync(sacc, fa, fb, sacc);
            }
            wmma::store_matrix_sync(Ss + tr * 16 * 68 + tc * 16, sacc, 68, wmma::mem_row_major);
        }
        __syncthreads();

        // ---- exp phase: thread t handles row t>>2, 16-col segment t&3 ----
        {
            const int row = t >> 2, seg = t & 3;
            const float* srow = Ss + row * 68 + seg * 16;
            __nv_bfloat16* erow = Es + row * 72 + seg * 16;
            float partial = 0.f;
#pragma unroll
            for (int j = 0; j < 16; j++) {
                float e = __expf(srow[j]);
                partial += e;
                erow[j] = __float2bfloat16(e);
            }
            rsp[row * 4 + seg] += partial;   // slot owned by this thread
        }
        __syncthreads();

        // ---- O phase: O += E @ V^T, B fragments straight from global ----
#pragma unroll
        for (int kk = 0; kk < 4; kk++) {
            wmma::fragment<wmma::matrix_b, 16, 16, 16, __nv_bfloat16, wmma::col_major> fb[2];
#pragma unroll
            for (int cg = 0; cg < 2; cg++)
                wmma::load_matrix_sync(fb[cg],
                    vb + (size_t)(c0 + cg * 16) * NPIX + n0 + kk * 16, NPIX);
#pragma unroll
            for (int mt = 0; mt < 4; mt++) {
                wmma::fragment<wmma::matrix_a, 16, 16, 16, __nv_bfloat16, wmma::row_major> fa;
                wmma::load_matrix_sync(fa, Es + mt * 16 * 72 + kk * 16, 72);
                wmma::mma_sync(oacc[mt][0], fa, fb[0], oacc[mt][0]);
                wmma::mma_sync(oacc[mt][1], fa, fb[1], oacc[mt][1]);
            }
        }
        // no sync needed: next S phase writes Ss only; Es rewritten only
        // after the next __syncthreads() (all warps past O phase by then)
    }
    __syncthreads();

    // ---- epilogue: fragments -> Ep, normalize, +mv, transposed store ----
#pragma unroll
    for (int mt = 0; mt < 4; mt++)
#pragma unroll
        for (int cg = 0; cg < 2; cg++)
            wmma::store_matrix_sync(Ep + mt * 16 * 260 + c0 + cg * 16,
                                    oacc[mt][cg], 260, wmma::mem_row_major);
    __syncthreads();

    const float* mvb = g_mv + b * CH;
    float* ob = out_t + (size_t)b * CH * NPIX + m0;
    const int mm = t & 63, g4 = t >> 6;
    const float inv = 1.f / (rsp[mm * 4] + rsp[mm * 4 + 1] +
                             rsp[mm * 4 + 2] + rsp[mm * 4 + 3]);
    for (int c = g4; c < CH; c += 4)
        ob[(size_t)c * NPIX + mm] = Ep[mm * 260 + c] * inv + mvb[c];
}

// ============================================================
extern "C" void kernel_launch(void* const* d_in, const int* in_sizes, int n_in,
                              void* d_out, int out_size)
{
    const float* x  = (const float*)d_in[0];
    const float* wq = (const float*)d_in[1];
    const float* wk = (const float*)d_in[3];
    const float* wv = (const float*)d_in[5];
    const float* bv = (const float*)d_in[6];
    const float* wm = (const float*)d_in[7];
    const float* bm = (const float*)d_in[8];
    float* out = (float*)d_out;

    const size_t half = (size_t)BATCH * CH * NPIX;  // 4,194,304
    float* tissue = out + ((size_t)out_size - half);
    if ((size_t)out_size >= 2 * half)
        cudaMemcpyAsync(out, x, half * sizeof(float), cudaMemcpyDeviceToDevice);

    proj_kernel<<<dim3(64, 6, 4), 256>>>(x, wq, wk, wv, bv, wm, bm);
    center_qk_kernel<<<dim3(64, 4), 256>>>();
    mask_softmax_kernel<<<4, 256>>>();
    mv_kernel<<<dim3(256, 4), 128>>>();

    const int SMEM_ATTN = 66560 + 1024 + 256;  // Ep + rsp + pad = 67840
    cudaFuncSetAttribute(attn_wmma_kernel, cudaFuncAttributeMaxDynamicSharedMemorySize,
                         SMEM_ATTN);
    attn_wmma_kernel<<<dim3(NPIX / 64, BATCH), 256, SMEM_ATTN>>>(tissue);
}